// round 1
// baseline (speedup 1.0000x reference)
#include <cuda_runtime.h>
#include <cstddef>

// Problem constants
#define BB   16
#define SS   1024
#define DM   256
#define H2N  4
#define DEP  32
#define BSN  (BB*SS)          // 16384
#define OUT_ELEMS   (BSN*DM)  // 4,194,304
#define ATTN_ELEMS  (BB*8*SS*SS) // 134,217,728

// ---------------- scratch (static device memory; no allocation) -------------
__device__ float g_Wq[256*256], g_Wk[256*256], g_Wv[256*256];
__device__ float g_bq[256],     g_bk[256],     g_bv[256];
__device__ float g_Q [BSN*DM];
__device__ float g_K [BSN*DM];
__device__ float g_V [BSN*DM];
__device__ float g_KT[BSN*DM];        // (b, n, s) transposed K projections
__device__ float g_O [BSN*DM];        // concat(o_dist, o_adj)
__device__ float g_Dsm[(size_t)BB*SS*SS]; // softmax(dist + neg)

// ---------------- weight packing: [Wd | Wa] -> 256x256 ----------------------
__global__ void pack_w(const float* __restrict__ Wd, const float* __restrict__ Wa,
                       const float* __restrict__ bd, const float* __restrict__ ba,
                       float* __restrict__ W, float* __restrict__ bias) {
    int k = blockIdx.x, n = threadIdx.x;
    W[k*256 + n] = (n < 128) ? Wd[k*128 + n] : Wa[k*128 + (n-128)];
    if (k == 0) bias[n] = (n < 128) ? bd[n] : ba[n-128];
}

// ---------------- GEMM: C[16384x256] = A[16384x256] @ W[256x256] + bias -----
// BM=128 BN=64 BK=16, 256 threads, 8x4 per-thread tile.
__global__ __launch_bounds__(256)
void gemm_kernel(const float* __restrict__ A, const float* __restrict__ W,
                 const float* __restrict__ bias, float* __restrict__ C) {
    __shared__ float As[16][132];   // k-major, padded
    __shared__ float Ws[16][64];
    const int t  = threadIdx.x;
    const int m0 = blockIdx.x * 128;
    const int n0 = blockIdx.y * 64;
    const int tn = t & 15, tm = t >> 4;

    float acc[8][4];
    #pragma unroll
    for (int i = 0; i < 8; ++i)
        #pragma unroll
        for (int j = 0; j < 4; ++j) acc[i][j] = 0.f;

    for (int k0 = 0; k0 < 256; k0 += 16) {
        __syncthreads();
        #pragma unroll
        for (int u = 0; u < 2; ++u) {                 // A tile: 512 float4
            int fi  = t + u*256;
            int row = fi >> 2, c4 = fi & 3;
            float4 v = *(const float4*)(A + (size_t)(m0+row)*256 + k0 + c4*4);
            As[c4*4+0][row] = v.x; As[c4*4+1][row] = v.y;
            As[c4*4+2][row] = v.z; As[c4*4+3][row] = v.w;
        }
        {                                             // W tile: 256 float4
            int k = t >> 4, n4 = t & 15;
            float4 v = *(const float4*)(W + (size_t)(k0+k)*256 + n0 + n4*4);
            *(float4*)(&Ws[k][n4*4]) = v;
        }
        __syncthreads();
        #pragma unroll
        for (int k = 0; k < 16; ++k) {
            float a[8];
            float4 b4 = *(const float4*)(&Ws[k][tn*4]);
            #pragma unroll
            for (int i = 0; i < 8; ++i) a[i] = As[k][tm*8 + i];
            #pragma unroll
            for (int i = 0; i < 8; ++i) {
                acc[i][0] = fmaf(a[i], b4.x, acc[i][0]);
                acc[i][1] = fmaf(a[i], b4.y, acc[i][1]);
                acc[i][2] = fmaf(a[i], b4.z, acc[i][2]);
                acc[i][3] = fmaf(a[i], b4.w, acc[i][3]);
            }
        }
    }
    float4 bb = *(const float4*)(bias + n0 + tn*4);
    #pragma unroll
    for (int i = 0; i < 8; ++i) {
        int m = m0 + tm*8 + i;
        float4 o;
        o.x = acc[i][0] + bb.x; o.y = acc[i][1] + bb.y;
        o.z = acc[i][2] + bb.z; o.w = acc[i][3] + bb.w;
        *(float4*)(C + (size_t)m*256 + n0 + tn*4) = o;
    }
}

// ---------------- transpose K: (b,s,n) -> (b,n,s) ---------------------------
__global__ void transpose_kernel(const float* __restrict__ in, float* __restrict__ out) {
    __shared__ float tile[32][33];
    const int b  = blockIdx.z;
    const int s0 = blockIdx.y * 32;
    const int n0 = blockIdx.x * 32;
    const int tx = threadIdx.x, ty = threadIdx.y;
    const float* src = in + ((size_t)b*SS + s0)*256 + n0;
    #pragma unroll
    for (int i = 0; i < 32; i += 8)
        tile[ty+i][tx] = src[(size_t)(ty+i)*256 + tx];
    __syncthreads();
    float* dst = out + ((size_t)b*256 + n0)*SS + s0;
    #pragma unroll
    for (int i = 0; i < 32; i += 8)
        dst[(size_t)(ty+i)*SS + tx] = tile[tx][ty+i];
}

// ---------------- dist softmax: Dsm[b,q,:] = softmax(dist + neg) ------------
__global__ void dist_softmax_kernel(const float* __restrict__ dist,
                                    const float* __restrict__ mask,
                                    float* __restrict__ out) {
    const int b = blockIdx.y, q = blockIdx.x, t = threadIdx.x;
    const float* drow = dist + ((size_t)b*SS + q)*SS;
    const float* mrow = mask + (size_t)b*SS;
    float e[4], s = 0.f;
    #pragma unroll
    for (int u = 0; u < 4; ++u) {
        int k = t + u*256;
        e[u] = __expf(drow[k] + mrow[k] * -1e9f);
        s += e[u];
    }
    #pragma unroll
    for (int off = 16; off; off >>= 1) s += __shfl_xor_sync(0xffffffffu, s, off);
    __shared__ float ws[8];
    if ((t & 31) == 0) ws[t >> 5] = s;
    __syncthreads();
    float tot = 0.f;
    #pragma unroll
    for (int w = 0; w < 8; ++w) tot += ws[w];
    const float inv = 1.f / tot;
    float* orow = out + ((size_t)b*SS + q)*SS;
    #pragma unroll
    for (int u = 0; u < 4; ++u) orow[t + u*256] = e[u] * inv;
}

// ---------------- fused attention: one CTA = 16 queries x 1 head ------------
// Phase A: logits = Q Ktile^T (full S row in registers, 8 rows x 8 strided keys/thread)
// Phase B: exp (no max-sub; masked -> exact 0), rowsum reduce, w = p*inv*extra,
//          write w to attn_w + smem.
// Phase C: out = w_sm @ V  (c-split register tiling, smem partial reduction)
__global__ __launch_bounds__(256, 2)
void attn_kernel(const float* __restrict__ Q, const float* __restrict__ KT,
                 const float* __restrict__ V, const float* __restrict__ mask,
                 const float* __restrict__ extra, float* __restrict__ attnw,
                 float* __restrict__ Obuf, int br) {
    extern __shared__ float sm[];
    float* q_sm = sm;                      // 16*32   = 512
    float* w_sm = sm + 512;                // 16*1025 = 16400 (padded)
    float* buf  = sm + 512 + 16400;        // 8208 (k-tile / v-stage / partials)
    float* pred = buf + 8208;              // 2*4*8 = 64

    const int t  = threadIdx.x;
    const int q0 = blockIdx.x * 16;
    const int h  = blockIdx.y;
    const int b  = blockIdx.z;
    const int coloff = br*128 + h*32;

    if (t < 128) {
        int r = t >> 3, c4 = t & 7;
        *(float4*)(q_sm + r*32 + c4*4) =
            *(const float4*)(Q + (size_t)(b*SS + q0 + r)*256 + coloff + c4*4);
    }

    const int rt = t >> 7;        // row group (0..1): rows rt*8..rt*8+7
    const int kt = t & 127;       // key group: keys kt + 128*j

    float acc[8][8];
    #pragma unroll
    for (int i = 0; i < 8; ++i)
        #pragma unroll
        for (int j = 0; j < 8; ++j) acc[i][j] = 0.f;

    const float* ktbase = KT + ((size_t)b*256 + coloff)*SS;
    for (int dc = 0; dc < 4; ++dc) {          // stream dims 8 at a time
        __syncthreads();
        const float4* src  = (const float4*)(ktbase + (size_t)dc*8*SS);
        float4*       dstk = (float4*)buf;    // buf as k_sm[8][1024]
        #pragma unroll
        for (int u = 0; u < 8; ++u) dstk[t + u*256] = src[t + u*256];
        __syncthreads();
        #pragma unroll
        for (int dd = 0; dd < 8; ++dd) {
            float qr[8], kk[8];
            #pragma unroll
            for (int i = 0; i < 8; ++i) qr[i] = q_sm[(rt*8+i)*32 + dc*8 + dd];
            #pragma unroll
            for (int j = 0; j < 8; ++j) kk[j] = buf[dd*1024 + kt + 128*j];
            #pragma unroll
            for (int i = 0; i < 8; ++i)
                #pragma unroll
                for (int j = 0; j < 8; ++j)
                    acc[i][j] = fmaf(qr[i], kk[j], acc[i][j]);
        }
    }

    // ---- softmax (masked lanes: exp(x - 1e9) underflows to exact 0) ----
    const float scale = 0.17677669529663688f;  // 1/sqrt(32)
    float neg[8];
    #pragma unroll
    for (int j = 0; j < 8; ++j) neg[j] = mask[b*SS + kt + 128*j] * -1e9f;

    float psum[8];
    #pragma unroll
    for (int i = 0; i < 8; ++i) {
        float s = 0.f;
        #pragma unroll
        for (int j = 0; j < 8; ++j) {
            float p = __expf(fmaf(acc[i][j], scale, neg[j]));
            acc[i][j] = p; s += p;
        }
        #pragma unroll
        for (int off = 16; off; off >>= 1) s += __shfl_xor_sync(0xffffffffu, s, off);
        psum[i] = s;
    }
    const int widx = (t >> 5) & 3;
    if ((t & 31) == 0) {
        #pragma unroll
        for (int i = 0; i < 8; ++i) pred[(rt*4 + widx)*8 + i] = psum[i];
    }
    __syncthreads();
    float inv[8];
    #pragma unroll
    for (int i = 0; i < 8; ++i)
        inv[i] = 1.f / (pred[(rt*4+0)*8+i] + pred[(rt*4+1)*8+i] +
                        pred[(rt*4+2)*8+i] + pred[(rt*4+3)*8+i]);

    // ---- weighting: w = p * inv * extra; write to attn_w + smem ----
    const int hg = br*4 + h;
    #pragma unroll
    for (int i = 0; i < 8; ++i) {
        int r = rt*8 + i;
        int qrow = q0 + r;
        const float* ex = extra + ((size_t)b*SS + qrow)*SS;
        float* wout = attnw ? attnw + (((size_t)(b*8 + hg)*SS + qrow)*SS) : nullptr;
        #pragma unroll
        for (int j = 0; j < 8; ++j) {
            int c = kt + 128*j;
            float wv = acc[i][j] * inv[i] * ex[c];
            w_sm[r*1025 + c] = wv;
            if (wout) wout[c] = wv;
        }
    }

    // ---- PV: out[16][32] = w_sm[16][1024] @ V[1024][32] ----
    const int cg = t & 15, dg = (t >> 4) & 7, rg = t >> 7;
    float oacc[8][4];
    #pragma unroll
    for (int i = 0; i < 8; ++i)
        #pragma unroll
        for (int jj = 0; jj < 4; ++jj) oacc[i][jj] = 0.f;

    const float* vbase = V + (size_t)b*SS*256 + coloff;
    for (int st = 0; st < 8; ++st) {
        __syncthreads();
        #pragma unroll
        for (int u = 0; u < 4; ++u) {          // V stage: 128 keys x 32 dims
            int fi = t + u*256;
            int row = fi >> 3, c4 = fi & 7;
            float4 v = *(const float4*)(vbase + (size_t)(st*128 + row)*256 + c4*4);
            float* d = buf + row*33 + c4*4;
            d[0] = v.x; d[1] = v.y; d[2] = v.z; d[3] = v.w;
        }
        __syncthreads();
        #pragma unroll
        for (int m8 = 0; m8 < 8; ++m8) {
            int cloc = cg + 16*m8;
            float vv[4], ww[8];
            #pragma unroll
            for (int jj = 0; jj < 4; ++jj) vv[jj] = buf[cloc*33 + dg*4 + jj];
            #pragma unroll
            for (int i = 0; i < 8; ++i) ww[i] = w_sm[(rg*8+i)*1025 + st*128 + cloc];
            #pragma unroll
            for (int i = 0; i < 8; ++i)
                #pragma unroll
                for (int jj = 0; jj < 4; ++jj)
                    oacc[i][jj] = fmaf(ww[i], vv[jj], oacc[i][jj]);
        }
    }
    __syncthreads();
    #pragma unroll
    for (int i = 0; i < 8; ++i)
        #pragma unroll
        for (int jj = 0; jj < 4; ++jj)
            buf[cg*513 + (rg*8+i)*32 + dg*4 + jj] = oacc[i][jj];
    __syncthreads();
    #pragma unroll
    for (int u = 0; u < 2; ++u) {
        int slot = t + u*256;
        float s = 0.f;
        #pragma unroll
        for (int g = 0; g < 16; ++g) s += buf[g*513 + slot];
        int r = slot >> 5, d = slot & 31;
        Obuf[(size_t)(b*SS + q0 + r)*256 + coloff + d] = s;
    }
}

// ---------------- launch --------------------------------------------------
extern "C" void kernel_launch(void* const* d_in, const int* in_sizes, int n_in,
                              void* d_out, int out_size) {
    const float* v_ori = (const float*)d_in[0];
    const float* k_ori = (const float*)d_in[1];
    const float* q_ori = (const float*)d_in[2];
    const float* mask  = (const float*)d_in[3];
    const float* adj   = (const float*)d_in[4];
    const float* dist  = (const float*)d_in[5];
    const float* Wq_d = (const float*)d_in[6];  const float* bq_d = (const float*)d_in[7];
    const float* Wk_d = (const float*)d_in[8];  const float* bk_d = (const float*)d_in[9];
    const float* Wv_d = (const float*)d_in[10]; const float* bv_d = (const float*)d_in[11];
    const float* Wq_a = (const float*)d_in[12]; const float* bq_a = (const float*)d_in[13];
    const float* Wk_a = (const float*)d_in[14]; const float* bk_a = (const float*)d_in[15];
    const float* Wv_a = (const float*)d_in[16]; const float* bv_a = (const float*)d_in[17];
    const float* Wo   = (const float*)d_in[18]; const float* bo   = (const float*)d_in[19];

    float* out   = (float*)d_out;
    float* attnw = (out_size >= OUT_ELEMS + ATTN_ELEMS) ? out + OUT_ELEMS : nullptr;

    float *pWq,*pWk,*pWv,*pbq,*pbk,*pbv,*pQ,*pK,*pV,*pKT,*pO,*pD;
    cudaGetSymbolAddress((void**)&pWq, g_Wq);
    cudaGetSymbolAddress((void**)&pWk, g_Wk);
    cudaGetSymbolAddress((void**)&pWv, g_Wv);
    cudaGetSymbolAddress((void**)&pbq, g_bq);
    cudaGetSymbolAddress((void**)&pbk, g_bk);
    cudaGetSymbolAddress((void**)&pbv, g_bv);
    cudaGetSymbolAddress((void**)&pQ,  g_Q);
    cudaGetSymbolAddress((void**)&pK,  g_K);
    cudaGetSymbolAddress((void**)&pV,  g_V);
    cudaGetSymbolAddress((void**)&pKT, g_KT);
    cudaGetSymbolAddress((void**)&pO,  g_O);
    cudaGetSymbolAddress((void**)&pD,  g_Dsm);

    pack_w<<<256, 256>>>(Wq_d, Wq_a, bq_d, bq_a, pWq, pbq);
    pack_w<<<256, 256>>>(Wk_d, Wk_a, bk_d, bk_a, pWk, pbk);
    pack_w<<<256, 256>>>(Wv_d, Wv_a, bv_d, bv_a, pWv, pbv);

    dim3 ggrid(128, 4);
    gemm_kernel<<<ggrid, 256>>>(q_ori, pWq, pbq, pQ);
    gemm_kernel<<<ggrid, 256>>>(k_ori, pWk, pbk, pK);
    gemm_kernel<<<ggrid, 256>>>(v_ori, pWv, pbv, pV);

    transpose_kernel<<<dim3(8, 32, 16), dim3(32, 8)>>>(pK, pKT);
    dist_softmax_kernel<<<dim3(1024, 16), 256>>>(dist, mask, pD);

    const int SMEM_BYTES = 25184 * 4;   // 100,736 B -> 2 CTAs/SM
    cudaFuncSetAttribute(attn_kernel, cudaFuncAttributeMaxDynamicSharedMemorySize, SMEM_BYTES);

    dim3 agrid(64, 4, 16);
    attn_kernel<<<agrid, 256, SMEM_BYTES>>>(pQ, pKT, pV, mask, pD,  attnw, pO, 0);
    attn_kernel<<<agrid, 256, SMEM_BYTES>>>(pQ, pKT, pV, mask, adj, attnw, pO, 1);

    gemm_kernel<<<ggrid, 256>>>(pO, Wo, bo, out);
}

// round 2
// speedup vs baseline: 1.0221x; 1.0221x over previous
#include <cuda_runtime.h>
#include <cstddef>

// Problem constants
#define BB   16
#define SS   1024
#define DM   256
#define BSN  (BB*SS)             // 16384
#define OUT_ELEMS   (BSN*DM)     // 4,194,304
#define ATTN_ELEMS  (BB*8*SS*SS) // 134,217,728

typedef unsigned long long u64;

__device__ __forceinline__ u64 pk2(float x, float y) {
    u64 r; asm("mov.b64 %0, {%1,%2};" : "=l"(r) : "f"(x), "f"(y)); return r;
}
__device__ __forceinline__ void up2(u64 v, float& x, float& y) {
    asm("mov.b64 {%0,%1}, %2;" : "=f"(x), "=f"(y) : "l"(v));
}
__device__ __forceinline__ void ffma2(u64& d, u64 a, u64 b) {
    asm("fma.rn.f32x2 %0, %1, %2, %0;" : "+l"(d) : "l"(a), "l"(b));
}

// ---------------- scratch (static device memory; no allocation) -------------
__device__ float g_Wq[256*256], g_Wk[256*256], g_Wv[256*256];
__device__ float g_bq[256],     g_bk[256],     g_bv[256];
__device__ float g_Q [BSN*DM];
__device__ float g_K [BSN*DM];
__device__ float g_V [BSN*DM];
__device__ float g_KT[BSN*DM];            // (b, n, s)
__device__ float g_O [BSN*DM];            // concat(o_dist, o_adj)
__device__ float g_Dsm[(size_t)BB*SS*SS]; // softmax(dist + neg)

// ---------------- weight packing: [Wd | Wa] -> 256x256 ----------------------
__global__ void pack_w(const float* __restrict__ Wd, const float* __restrict__ Wa,
                       const float* __restrict__ bd, const float* __restrict__ ba,
                       float* __restrict__ W, float* __restrict__ bias) {
    int k = blockIdx.x, n = threadIdx.x;
    W[k*256 + n] = (n < 128) ? Wd[k*128 + n] : Wa[k*128 + (n-128)];
    if (k == 0) bias[n] = (n < 128) ? bd[n] : ba[n-128];
}

// ---------------- GEMM: C[16384x256] = A[16384x256] @ W[256x256] + bias -----
// BM=128 BN=128 BK=16, 256 threads, 8x8/thread via FFMA2 (rows paired).
__global__ __launch_bounds__(256)
void gemm2_kernel(const float* __restrict__ A, const float* __restrict__ W,
                  const float* __restrict__ bias, float* __restrict__ C) {
    __shared__ float As[16][132];   // k-major, padded
    __shared__ float Ws[16][132];
    const int t  = threadIdx.x;
    const int m0 = blockIdx.x * 128;
    const int n0 = blockIdx.y * 128;
    const int tn = t & 15, tm = t >> 4;

    u64 acc[4][8];
    #pragma unroll
    for (int p = 0; p < 4; ++p)
        #pragma unroll
        for (int j = 0; j < 8; ++j) acc[p][j] = 0ull;

    for (int k0 = 0; k0 < 256; k0 += 16) {
        __syncthreads();
        #pragma unroll
        for (int u = 0; u < 2; ++u) {                 // A tile: 512 float4
            int fi  = t + u*256;
            int row = fi >> 2, c4 = fi & 3;
            float4 v = *(const float4*)(A + (size_t)(m0+row)*256 + k0 + c4*4);
            As[c4*4+0][row] = v.x; As[c4*4+1][row] = v.y;
            As[c4*4+2][row] = v.z; As[c4*4+3][row] = v.w;
        }
        #pragma unroll
        for (int u = 0; u < 2; ++u) {                 // W tile: 512 float4
            int fi = t + u*256;
            int k = fi >> 5, n4 = fi & 31;
            *(float4*)(&Ws[k][n4*4]) =
                *(const float4*)(W + (size_t)(k0+k)*256 + n0 + n4*4);
        }
        __syncthreads();
        #pragma unroll
        for (int k = 0; k < 16; ++k) {
            ulonglong2 a01 = *(const ulonglong2*)(&As[k][tm*8]);
            ulonglong2 a23 = *(const ulonglong2*)(&As[k][tm*8 + 4]);
            u64 ap[4] = {a01.x, a01.y, a23.x, a23.y};
            float4 w0 = *(const float4*)(&Ws[k][tn*8]);
            float4 w1 = *(const float4*)(&Ws[k][tn*8 + 4]);
            u64 bd[8];
            bd[0] = pk2(w0.x, w0.x); bd[1] = pk2(w0.y, w0.y);
            bd[2] = pk2(w0.z, w0.z); bd[3] = pk2(w0.w, w0.w);
            bd[4] = pk2(w1.x, w1.x); bd[5] = pk2(w1.y, w1.y);
            bd[6] = pk2(w1.z, w1.z); bd[7] = pk2(w1.w, w1.w);
            #pragma unroll
            for (int p = 0; p < 4; ++p)
                #pragma unroll
                for (int j = 0; j < 8; ++j)
                    ffma2(acc[p][j], ap[p], bd[j]);
        }
    }
    float4 b0 = *(const float4*)(bias + n0 + tn*8);
    float4 b1 = *(const float4*)(bias + n0 + tn*8 + 4);
    float bb[8] = {b0.x, b0.y, b0.z, b0.w, b1.x, b1.y, b1.z, b1.w};
    #pragma unroll
    for (int p = 0; p < 4; ++p) {
        float lo[8], hi[8];
        #pragma unroll
        for (int j = 0; j < 8; ++j) up2(acc[p][j], lo[j], hi[j]);
        int r0 = m0 + tm*8 + p*2;
        float4 o;
        o.x = lo[0]+bb[0]; o.y = lo[1]+bb[1]; o.z = lo[2]+bb[2]; o.w = lo[3]+bb[3];
        *(float4*)(C + (size_t)r0*256 + n0 + tn*8) = o;
        o.x = lo[4]+bb[4]; o.y = lo[5]+bb[5]; o.z = lo[6]+bb[6]; o.w = lo[7]+bb[7];
        *(float4*)(C + (size_t)r0*256 + n0 + tn*8 + 4) = o;
        o.x = hi[0]+bb[0]; o.y = hi[1]+bb[1]; o.z = hi[2]+bb[2]; o.w = hi[3]+bb[3];
        *(float4*)(C + (size_t)(r0+1)*256 + n0 + tn*8) = o;
        o.x = hi[4]+bb[4]; o.y = hi[5]+bb[5]; o.z = hi[6]+bb[6]; o.w = hi[7]+bb[7];
        *(float4*)(C + (size_t)(r0+1)*256 + n0 + tn*8 + 4) = o;
    }
}

// ---------------- transpose K: (b,s,n) -> (b,n,s) ---------------------------
__global__ void transpose_kernel(const float* __restrict__ in, float* __restrict__ out) {
    __shared__ float tile[32][33];
    const int b  = blockIdx.z;
    const int s0 = blockIdx.y * 32;
    const int n0 = blockIdx.x * 32;
    const int tx = threadIdx.x, ty = threadIdx.y;
    const float* src = in + ((size_t)b*SS + s0)*256 + n0;
    #pragma unroll
    for (int i = 0; i < 32; i += 8)
        tile[ty+i][tx] = src[(size_t)(ty+i)*256 + tx];
    __syncthreads();
    float* dst = out + ((size_t)b*256 + n0)*SS + s0;
    #pragma unroll
    for (int i = 0; i < 32; i += 8)
        dst[(size_t)(ty+i)*SS + tx] = tile[tx][ty+i];
}

// ---------------- dist softmax: Dsm[b,q,:] = softmax(dist + neg) ------------
__global__ void dist_softmax_kernel(const float* __restrict__ dist,
                                    const float* __restrict__ mask,
                                    float* __restrict__ out) {
    const int b = blockIdx.y, q = blockIdx.x, t = threadIdx.x;
    const float* drow = dist + ((size_t)b*SS + q)*SS;
    const float* mrow = mask + (size_t)b*SS;
    float e[4], s = 0.f;
    #pragma unroll
    for (int u = 0; u < 4; ++u) {
        int k = t + u*256;
        e[u] = __expf(drow[k] + mrow[k] * -1e9f);
        s += e[u];
    }
    #pragma unroll
    for (int off = 16; off; off >>= 1) s += __shfl_xor_sync(0xffffffffu, s, off);
    __shared__ float ws[8];
    if ((t & 31) == 0) ws[t >> 5] = s;
    __syncthreads();
    float tot = 0.f;
    #pragma unroll
    for (int w = 0; w < 8; ++w) tot += ws[w];
    const float inv = 1.f / tot;
    float* orow = out + ((size_t)b*SS + q)*SS;
    #pragma unroll
    for (int u = 0; u < 4; ++u) orow[t + u*256] = e[u] * inv;
}

// ---------------- fused attention (FFMA2): CTA = 16 queries x 1 head --------
// Thread owns 8 CONTIGUOUS keys c = (t&127)*8 + j -> vector LDS/LDG/STG.
// smem layout (floats): q_dup[16][64] | w_sm[16][1032] | buf[8208] | pred[64]
__global__ __launch_bounds__(256, 2)
void attn_kernel(const float* __restrict__ Q, const float* __restrict__ KT,
                 const float* __restrict__ V, const float* __restrict__ mask,
                 const float* __restrict__ extraD, const float* __restrict__ extraA,
                 float* __restrict__ attnw, float* __restrict__ Obuf) {
    extern __shared__ float sm[];
    float* q_dup = sm;                 // 1024
    float* w_sm  = sm + 1024;          // 16*1032 = 16512
    float* buf   = sm + 17536;         // 8208
    float* pred  = sm + 25744;         // 64

    const int t  = threadIdx.x;
    const int q0 = blockIdx.x * 16;
    const int hg = blockIdx.y;         // 0..7 ; br = hg>>2
    const int b  = blockIdx.z;
    const int coloff = hg * 32;
    const float* extra = (hg >= 4) ? extraA : extraD;

    if (t < 128) {                     // Q as duplicated pairs (q,q)
        int r = t >> 3, c4 = t & 7;
        float4 v = *(const float4*)(Q + (size_t)(b*SS + q0 + r)*256 + coloff + c4*4);
        float* d = q_dup + r*64 + c4*8;
        float4 o;
        o.x = v.x; o.y = v.x; o.z = v.y; o.w = v.y; *(float4*)(d)     = o;
        o.x = v.z; o.y = v.z; o.z = v.w; o.w = v.w; *(float4*)(d + 4) = o;
    }

    const int rt = t >> 7;            // row group: rows rt*8..rt*8+7
    const int kt = t & 127;           // keys kt*8 .. kt*8+7

    u64 acc[8][4];
    #pragma unroll
    for (int i = 0; i < 8; ++i)
        #pragma unroll
        for (int jp = 0; jp < 4; ++jp) acc[i][jp] = 0ull;

    // ---- QK^T ----
    const float* ktbase = KT + ((size_t)b*256 + coloff)*SS;
    for (int dc = 0; dc < 4; ++dc) {
        __syncthreads();
        const float4* src  = (const float4*)(ktbase + (size_t)dc*8*SS);
        float4*       dstk = (float4*)buf;          // buf as k_sm[8][1024]
        #pragma unroll
        for (int u = 0; u < 8; ++u) dstk[t + u*256] = src[t + u*256];
        __syncthreads();
        #pragma unroll
        for (int dd = 0; dd < 8; ++dd) {
            ulonglong2 k01 = *(const ulonglong2*)(&buf[dd*1024 + kt*8]);
            ulonglong2 k23 = *(const ulonglong2*)(&buf[dd*1024 + kt*8 + 4]);
            u64 kp[4] = {k01.x, k01.y, k23.x, k23.y};
            #pragma unroll
            for (int i = 0; i < 8; ++i) {
                u64 qd = *(const u64*)(&q_dup[(rt*8+i)*64 + (dc*8+dd)*2]);
                #pragma unroll
                for (int jp = 0; jp < 4; ++jp) ffma2(acc[i][jp], qd, kp[jp]);
            }
        }
    }

    // ---- softmax (masked lanes underflow to exact 0) ----
    const float scale = 0.17677669529663688f;  // 1/sqrt(32)
    float neg[8];
    {
        float4 m0v = *(const float4*)(mask + b*SS + kt*8);
        float4 m1v = *(const float4*)(mask + b*SS + kt*8 + 4);
        neg[0]=m0v.x*-1e9f; neg[1]=m0v.y*-1e9f; neg[2]=m0v.z*-1e9f; neg[3]=m0v.w*-1e9f;
        neg[4]=m1v.x*-1e9f; neg[5]=m1v.y*-1e9f; neg[6]=m1v.z*-1e9f; neg[7]=m1v.w*-1e9f;
    }
    float psum[8];
    #pragma unroll
    for (int i = 0; i < 8; ++i) {
        float e[8];
        #pragma unroll
        for (int jp = 0; jp < 4; ++jp) up2(acc[i][jp], e[2*jp], e[2*jp+1]);
        float s = 0.f;
        #pragma unroll
        for (int j = 0; j < 8; ++j) {
            e[j] = __expf(fmaf(e[j], scale, neg[j]));
            s += e[j];
        }
        #pragma unroll
        for (int jp = 0; jp < 4; ++jp) acc[i][jp] = pk2(e[2*jp], e[2*jp+1]);
        #pragma unroll
        for (int off = 16; off; off >>= 1) s += __shfl_xor_sync(0xffffffffu, s, off);
        psum[i] = s;
    }
    const int widx = (t >> 5) & 3;
    if ((t & 31) == 0) {
        #pragma unroll
        for (int i = 0; i < 8; ++i) pred[(rt*4 + widx)*8 + i] = psum[i];
    }
    __syncthreads();
    float inv[8];
    #pragma unroll
    for (int i = 0; i < 8; ++i)
        inv[i] = 1.f / (pred[(rt*4+0)*8+i] + pred[(rt*4+1)*8+i] +
                        pred[(rt*4+2)*8+i] + pred[(rt*4+3)*8+i]);

    // ---- weighting: w = p * inv * extra -> w_sm + attn_w (vectorized) ----
    #pragma unroll
    for (int i = 0; i < 8; ++i) {
        int r = rt*8 + i;
        int qrow = q0 + r;
        const float* ex = extra + ((size_t)b*SS + qrow)*SS + kt*8;
        float4 e0 = *(const float4*)(ex);
        float4 e1 = *(const float4*)(ex + 4);
        float ev[8] = {e0.x, e0.y, e0.z, e0.w, e1.x, e1.y, e1.z, e1.w};
        float w[8];
        #pragma unroll
        for (int jp = 0; jp < 4; ++jp) up2(acc[i][jp], w[2*jp], w[2*jp+1]);
        float4 o0, o1;
        o0.x = w[0]*inv[i]*ev[0]; o0.y = w[1]*inv[i]*ev[1];
        o0.z = w[2]*inv[i]*ev[2]; o0.w = w[3]*inv[i]*ev[3];
        o1.x = w[4]*inv[i]*ev[4]; o1.y = w[5]*inv[i]*ev[5];
        o1.z = w[6]*inv[i]*ev[6]; o1.w = w[7]*inv[i]*ev[7];
        *(float4*)(&w_sm[r*1032 + kt*8])     = o0;
        *(float4*)(&w_sm[r*1032 + kt*8 + 4]) = o1;
        if (attnw) {
            float* wout = attnw + (((size_t)(b*8 + hg)*SS + qrow)*SS) + kt*8;
            *(float4*)(wout)     = o0;
            *(float4*)(wout + 4) = o1;
        }
    }

    // ---- PV: out[16][32] = w_sm[16][1024] @ V[1024][32] ----
    const int cg = t & 15, dg = (t >> 4) & 7, rg = t >> 7;
    u64 oac[8][2];
    #pragma unroll
    for (int i = 0; i < 8; ++i) { oac[i][0] = 0ull; oac[i][1] = 0ull; }

    const float* vbase = V + (size_t)b*SS*256 + coloff;
    for (int st = 0; st < 8; ++st) {
        __syncthreads();
        #pragma unroll
        for (int u = 0; u < 4; ++u) {          // V stage: 128 keys x 32 dims, pad 36
            int fi = t + u*256;
            int row = fi >> 3, c4 = fi & 7;
            *(float4*)(&buf[row*36 + c4*4]) =
                *(const float4*)(vbase + (size_t)(st*128 + row)*256 + c4*4);
        }
        __syncthreads();
        #pragma unroll
        for (int m8 = 0; m8 < 8; ++m8) {
            int cloc = cg + 16*m8;
            ulonglong2 vp = *(const ulonglong2*)(&buf[cloc*36 + dg*4]);
            u64 vpair0 = vp.x, vpair1 = vp.y;
            #pragma unroll
            for (int i = 0; i < 8; ++i) {
                float w = w_sm[(rg*8+i)*1032 + st*128 + cloc];
                u64 wd = pk2(w, w);
                ffma2(oac[i][0], wd, vpair0);
                ffma2(oac[i][1], wd, vpair1);
            }
        }
    }
    __syncthreads();
    #pragma unroll
    for (int i = 0; i < 8; ++i) {
        float o0, o1, o2, o3;
        up2(oac[i][0], o0, o1);
        up2(oac[i][1], o2, o3);
        float* d = &buf[cg*513 + (rg*8+i)*32 + dg*4];
        d[0] = o0; d[1] = o1; d[2] = o2; d[3] = o3;
    }
    __syncthreads();
    #pragma unroll
    for (int u = 0; u < 2; ++u) {
        int slot = t + u*256;
        float s = 0.f;
        #pragma unroll
        for (int g = 0; g < 16; ++g) s += buf[g*513 + slot];
        int r = slot >> 5, d = slot & 31;
        Obuf[(size_t)(b*SS + q0 + r)*256 + coloff + d] = s;
    }
}

// ---------------- launch --------------------------------------------------
extern "C" void kernel_launch(void* const* d_in, const int* in_sizes, int n_in,
                              void* d_out, int out_size) {
    const float* v_ori = (const float*)d_in[0];
    const float* k_ori = (const float*)d_in[1];
    const float* q_ori = (const float*)d_in[2];
    const float* mask  = (const float*)d_in[3];
    const float* adj   = (const float*)d_in[4];
    const float* dist  = (const float*)d_in[5];
    const float* Wq_d = (const float*)d_in[6];  const float* bq_d = (const float*)d_in[7];
    const float* Wk_d = (const float*)d_in[8];  const float* bk_d = (const float*)d_in[9];
    const float* Wv_d = (const float*)d_in[10]; const float* bv_d = (const float*)d_in[11];
    const float* Wq_a = (const float*)d_in[12]; const float* bq_a = (const float*)d_in[13];
    const float* Wk_a = (const float*)d_in[14]; const float* bk_a = (const float*)d_in[15];
    const float* Wv_a = (const float*)d_in[16]; const float* bv_a = (const float*)d_in[17];
    const float* Wo   = (const float*)d_in[18]; const float* bo   = (const float*)d_in[19];

    float* out   = (float*)d_out;
    float* attnw = (out_size >= OUT_ELEMS + ATTN_ELEMS) ? out + OUT_ELEMS : nullptr;

    float *pWq,*pWk,*pWv,*pbq,*pbk,*pbv,*pQ,*pK,*pV,*pKT,*pO,*pD;
    cudaGetSymbolAddress((void**)&pWq, g_Wq);
    cudaGetSymbolAddress((void**)&pWk, g_Wk);
    cudaGetSymbolAddress((void**)&pWv, g_Wv);
    cudaGetSymbolAddress((void**)&pbq, g_bq);
    cudaGetSymbolAddress((void**)&pbk, g_bk);
    cudaGetSymbolAddress((void**)&pbv, g_bv);
    cudaGetSymbolAddress((void**)&pQ,  g_Q);
    cudaGetSymbolAddress((void**)&pK,  g_K);
    cudaGetSymbolAddress((void**)&pV,  g_V);
    cudaGetSymbolAddress((void**)&pKT, g_KT);
    cudaGetSymbolAddress((void**)&pO,  g_O);
    cudaGetSymbolAddress((void**)&pD,  g_Dsm);

    pack_w<<<256, 256>>>(Wq_d, Wq_a, bq_d, bq_a, pWq, pbq);
    pack_w<<<256, 256>>>(Wk_d, Wk_a, bk_d, bk_a, pWk, pbk);
    pack_w<<<256, 256>>>(Wv_d, Wv_a, bv_d, bv_a, pWv, pbv);

    dim3 ggrid(128, 2);
    gemm2_kernel<<<ggrid, 256>>>(q_ori, pWq, pbq, pQ);
    gemm2_kernel<<<ggrid, 256>>>(k_ori, pWk, pbk, pK);
    gemm2_kernel<<<ggrid, 256>>>(v_ori, pWv, pbv, pV);

    transpose_kernel<<<dim3(8, 32, 16), dim3(32, 8)>>>(pK, pKT);
    dist_softmax_kernel<<<dim3(1024, 16), 256>>>(dist, mask, pD);

    const int SMEM_BYTES = 25808 * 4;   // 103,232 B -> 2 CTAs/SM
    cudaFuncSetAttribute(attn_kernel, cudaFuncAttributeMaxDynamicSharedMemorySize, SMEM_BYTES);

    dim3 agrid(64, 8, 16);
    attn_kernel<<<agrid, 256, SMEM_BYTES>>>(pQ, pKT, pV, mask, pD, adj, attnw, pO);

    gemm2_kernel<<<ggrid, 256>>>(pO, Wo, bo, out);
}